// round 1
// baseline (speedup 1.0000x reference)
#include <cuda_runtime.h>
#include <cstdint>

// Problem constants
#define BB 4
#define NN 2048
#define KK 32
#define CIN 16
#define COUT 32
#define HH 32
#define RTOT (BB*NN*KK)      // 262144
#define MTOT (BB*NN)         // 8192
#define EPS 1e-5f
#define FULLMASK 0xffffffffu

// ---------------- scratch (device globals; no allocation allowed) ----------------
__device__ __align__(16) float g_h1[(size_t)RTOT*HH];     // 32 MB
__device__ __align__(16) float g_h2[(size_t)RTOT*HH];     // 32 MB
__device__ __align__(16) float g_Q[(size_t)MTOT*HH*COUT]; // 32 MB  Q[b,m,j,o]
__device__ __align__(16) float g_pb3[(size_t)MTOT*COUT];  // 1 MB
__device__ int   g_idx[RTOT];                             // 1 MB
__device__ float g_part[2048*64];                         // stats partials
__device__ float g_sc1[64];                               // scale/shift for BN1
__device__ float g_sc2[64];
__device__ float g_sc3[64];

// ---------------- KNN: warp bitonic top-32 ----------------
__device__ __forceinline__ void cas_pair(float& d, int& i, int stride, bool up, int lane) {
    float od = __shfl_xor_sync(FULLMASK, d, stride);
    int   oi = __shfl_xor_sync(FULLMASK, i, stride);
    bool otherSmaller = (od < d) || (od == d && oi < i);
    bool lower = ((lane & stride) == 0);
    bool take = (lower == up) ? otherSmaller : !otherSmaller;
    if (take) { d = od; i = oi; }
}

__device__ __forceinline__ void sort32(float& d, int& i, bool asc, int lane) {
#pragma unroll
    for (int k = 2; k <= 32; k <<= 1) {
        bool up = (((lane & k) == 0) == asc);
#pragma unroll
        for (int s = k >> 1; s > 0; s >>= 1) cas_pair(d, i, s, up, lane);
    }
}

__device__ __forceinline__ void merge32(float& d, int& i, int lane) {
#pragma unroll
    for (int s = 16; s > 0; s >>= 1) cas_pair(d, i, s, true, lane);
}

__global__ __launch_bounds__(256) void knn_kernel(const float* __restrict__ xyz) {
    __shared__ float sx[NN], sy[NN], sz[NN], sq[NN];
    int b = blockIdx.x >> 8;               // 256 blocks per batch
    int nbase = (blockIdx.x & 255) * 8;
    int tid = threadIdx.x;
    for (int i = tid; i < NN; i += 256) {
        const float* p = xyz + ((size_t)b * NN + i) * 3;
        float x = p[0], y = p[1], z = p[2];
        sx[i] = x; sy[i] = y; sz[i] = z; sq[i] = x * x + y * y + z * z;
    }
    __syncthreads();
    int w = tid >> 5, lane = tid & 31;
    int n = nbase + w;
    float qx = sx[n], qy = sy[n], qz = sz[n], qs = sq[n];

    // chunk 0 -> initial sorted top-32
    int j = lane;
    float d = fmaf(-2.f, qx * sx[j] + qy * sy[j] + qz * sz[j], qs + sq[j]);
    int di = j;
    sort32(d, di, true, lane);

    for (int c = 1; c < 64; c++) {
        j = c * 32 + lane;
        float cd = fmaf(-2.f, qx * sx[j] + qy * sy[j] + qz * sz[j], qs + sq[j]);
        int ci = j;
        float kmax = __shfl_sync(FULLMASK, d, 31);
        if (__any_sync(FULLMASK, cd < kmax)) {
            sort32(cd, ci, false, lane);  // descending
            bool less = (cd < d) || (cd == d && ci < di);
            if (less) { d = cd; di = ci; }
            merge32(d, di, lane);
        }
    }
    g_idx[((size_t)b * NN + n) * KK + lane] = di;
}

// ---------------- stage1: h1 = relu(rel @ W1 + b1) ----------------
__global__ __launch_bounds__(128) void stage1_kernel(const float* __restrict__ xyz,
                                                     const float* __restrict__ W1,
                                                     const float* __restrict__ b1) {
    int r = blockIdx.x * 128 + threadIdx.x;
    int b = r >> 16;           // N*K = 65536
    int rem = r & 65535;
    int n = rem >> 5;
    int m = g_idx[r];
    const float* pc = xyz + ((size_t)b * NN + n) * 3;
    const float* pn = xyz + ((size_t)b * NN + m) * 3;
    float rx = pn[0] - pc[0], ry = pn[1] - pc[1], rz = pn[2] - pc[2];
    float4* out = (float4*)(g_h1 + (size_t)r * HH);
#pragma unroll
    for (int q = 0; q < 8; q++) {
        float4 v;
        int i0 = q * 4;
        v.x = fmaxf(fmaf(rx, __ldg(W1 + i0 + 0), fmaf(ry, __ldg(W1 + 32 + i0 + 0), fmaf(rz, __ldg(W1 + 64 + i0 + 0), __ldg(b1 + i0 + 0)))), 0.f);
        v.y = fmaxf(fmaf(rx, __ldg(W1 + i0 + 1), fmaf(ry, __ldg(W1 + 32 + i0 + 1), fmaf(rz, __ldg(W1 + 64 + i0 + 1), __ldg(b1 + i0 + 1)))), 0.f);
        v.z = fmaxf(fmaf(rx, __ldg(W1 + i0 + 2), fmaf(ry, __ldg(W1 + 32 + i0 + 2), fmaf(rz, __ldg(W1 + 64 + i0 + 2), __ldg(b1 + i0 + 2)))), 0.f);
        v.w = fmaxf(fmaf(rx, __ldg(W1 + i0 + 3), fmaf(ry, __ldg(W1 + 32 + i0 + 3), fmaf(rz, __ldg(W1 + 64 + i0 + 3), __ldg(b1 + i0 + 3)))), 0.f);
        out[q] = v;
    }
}

// ---------------- stats: per-channel sum & sumsq (deterministic) ----------------
__global__ __launch_bounds__(128) void stats_kernel(const float* __restrict__ X, int nrows) {
    int tid = threadIdx.x;
    int c = tid & 31, g = tid >> 5;
    float s = 0.f, s2 = 0.f;
    for (int r = blockIdx.x * 4 + g; r < nrows; r += 2048 * 4) {
        float v = X[(size_t)r * 32 + c];
        s += v; s2 = fmaf(v, v, s2);
    }
    __shared__ float sh[128], sh2[128];
    sh[tid] = s; sh2[tid] = s2;
    __syncthreads();
    if (tid < 32) {
        float a  = ((sh[tid]  + sh[tid + 32])  + sh[tid + 64])  + sh[tid + 96];
        float a2 = ((sh2[tid] + sh2[tid + 32]) + sh2[tid + 64]) + sh2[tid + 96];
        g_part[blockIdx.x * 64 + tid]      = a;
        g_part[blockIdx.x * 64 + 32 + tid] = a2;
    }
}

// ---------------- finalize: mean/var -> scale/shift ----------------
__global__ __launch_bounds__(256) void finalize_kernel(float invcount,
                                                       const float* __restrict__ gamma,
                                                       const float* __restrict__ beta,
                                                       float* __restrict__ scsh) {
    int c = blockIdx.x;
    int tid = threadIdx.x;
    float s = 0.f, s2 = 0.f;
    for (int i = tid; i < 2048; i += 256) {
        s  += g_part[i * 64 + c];
        s2 += g_part[i * 64 + 32 + c];
    }
    __shared__ float sh[256], sh2[256];
    sh[tid] = s; sh2[tid] = s2;
    __syncthreads();
    for (int st = 128; st > 0; st >>= 1) {
        if (tid < st) { sh[tid] += sh[tid + st]; sh2[tid] += sh2[tid + st]; }
        __syncthreads();
    }
    if (tid == 0) {
        float mean = sh[0] * invcount;
        float var  = sh2[0] * invcount - mean * mean;
        float inv  = rsqrtf(var + EPS);
        float sc   = gamma[c] * inv;
        scsh[c]      = sc;
        scsh[32 + c] = fmaf(-mean, sc, beta[c]);
    }
}

// ---------------- stage2: h2 = relu(BN1(h1) @ W2 + b2) ----------------
__global__ __launch_bounds__(128) void stage2_kernel(const float* __restrict__ W2,
                                                     const float* __restrict__ b2) {
    __shared__ float4 sW2[256];          // W2[j][i] as float4 along i
    __shared__ float ssc[32], ssh[32];
    int tid = threadIdx.x;
    if (tid < 128) {
        sW2[tid]       = ((const float4*)W2)[tid];
        sW2[tid + 128] = ((const float4*)W2)[tid + 128];
    }
    if (tid < 32) { ssc[tid] = g_sc1[tid]; ssh[tid] = g_sc1[32 + tid]; }
    __syncthreads();

    int r = blockIdx.x * 128 + tid;
    const float4* in = (const float4*)(g_h1 + (size_t)r * HH);
    float h[32];
#pragma unroll
    for (int q = 0; q < 8; q++) {
        float4 v = in[q];
        h[q * 4 + 0] = fmaf(v.x, ssc[q * 4 + 0], ssh[q * 4 + 0]);
        h[q * 4 + 1] = fmaf(v.y, ssc[q * 4 + 1], ssh[q * 4 + 1]);
        h[q * 4 + 2] = fmaf(v.z, ssc[q * 4 + 2], ssh[q * 4 + 2]);
        h[q * 4 + 3] = fmaf(v.w, ssc[q * 4 + 3], ssh[q * 4 + 3]);
    }
    float4 acc[8];
#pragma unroll
    for (int q = 0; q < 8; q++) acc[q] = __ldg(((const float4*)b2) + q);
#pragma unroll
    for (int j = 0; j < 32; j++) {
        float hv = h[j];
#pragma unroll
        for (int q = 0; q < 8; q++) {
            float4 wv = sW2[j * 8 + q];
            acc[q].x = fmaf(hv, wv.x, acc[q].x);
            acc[q].y = fmaf(hv, wv.y, acc[q].y);
            acc[q].z = fmaf(hv, wv.z, acc[q].z);
            acc[q].w = fmaf(hv, wv.w, acc[q].w);
        }
    }
    float4* out = (float4*)(g_h2 + (size_t)r * HH);
#pragma unroll
    for (int q = 0; q < 8; q++) {
        float4 v = acc[q];
        v.x = fmaxf(v.x, 0.f); v.y = fmaxf(v.y, 0.f);
        v.z = fmaxf(v.z, 0.f); v.w = fmaxf(v.w, 0.f);
        out[q] = v;
    }
}

// ---------------- qcompute: Q[b,m,j,o] = sum_c p[c] * W3[j, c*32+o]; pb3 ----------------
__global__ __launch_bounds__(256) void qcompute_kernel(const float* __restrict__ points,
                                                       const float* __restrict__ W3,
                                                       const float* __restrict__ b3) {
    __shared__ float sW3[16 * 512];   // 32 KB: half of W3 rows
    __shared__ float sp[8][16];
    int tid = threadIdx.x;
    int mg0 = blockIdx.x * 8;
    if (tid < 128) {
        int m = tid >> 4, c = tid & 15;
        sp[m][c] = points[(size_t)(mg0 + m) * CIN + c];
    }
    for (int half = 0; half < 2; half++) {
        __syncthreads();   // protect sW3 reuse (and sp on first pass)
        for (int t = tid; t < 8192; t += 256) sW3[t] = W3[half * 8192 + t];
        __syncthreads();
        for (int t = tid; t < 4096; t += 256) {
            int m = t >> 9;
            int jo = t & 511;
            int jl = jo >> 5, o = jo & 31;
            float acc = 0.f;
#pragma unroll
            for (int c = 0; c < 16; c++)
                acc = fmaf(sp[m][c], sW3[jl * 512 + c * 32 + o], acc);
            g_Q[(size_t)(mg0 + m) * 1024 + (half * 16 + jl) * 32 + o] = acc;
        }
    }
    __syncthreads();
    {   // pb3: 8*32 outputs, one per thread
        int m = tid >> 5, o = tid & 31;
        float acc = 0.f;
#pragma unroll
        for (int c = 0; c < 16; c++)
            acc = fmaf(sp[m][c], __ldg(b3 + c * 32 + o), acc);
        g_pb3[(size_t)(mg0 + m) * 32 + o] = acc;
    }
}

// ---------------- stage3: out[b,n,o] = max_k ( h2n[k] . Q[b,idx,:,o] + pb3 ) ----------------
__global__ __launch_bounds__(256) void stage3_kernel(float* __restrict__ out) {
    __shared__ float sh2n[32][32];
    __shared__ int   sidx[32];
    __shared__ float ssc[32], ssh[32];
    __shared__ float wmax[8][32];
    int tid = threadIdx.x;
    int q = blockIdx.x;                    // b*N + n
    size_t r0 = (size_t)q * KK;            // first MLP row of this query
    if (tid < 32) {
        ssc[tid] = g_sc2[tid];
        ssh[tid] = g_sc2[32 + tid];
        sidx[tid] = g_idx[r0 + tid];
    }
    __syncthreads();
    for (int t = tid; t < 1024; t += 256) {
        int k = t >> 5, jj = t & 31;
        sh2n[k][jj] = fmaf(g_h2[(r0 + k) * 32 + jj], ssc[jj], ssh[jj]);
    }
    __syncthreads();

    int w = tid >> 5, o = tid & 31;
    int b = q >> 11;
    float vmax = -3.4e38f;
#pragma unroll
    for (int kk = 0; kk < 4; kk++) {
        int k = w + kk * 8;
        int m = sidx[k];
        size_t mg = ((size_t)b << 11) + m;
        const float* Qp = g_Q + mg * 1024 + o;
        float acc = g_pb3[mg * 32 + o];
#pragma unroll
        for (int jj = 0; jj < 32; jj++)
            acc = fmaf(sh2n[k][jj], Qp[jj * 32], acc);
        vmax = fmaxf(vmax, acc);
    }
    wmax[w][o] = vmax;
    __syncthreads();
    if (tid < 32) {
        float v = wmax[0][tid];
#pragma unroll
        for (int i = 1; i < 8; i++) v = fmaxf(v, wmax[i][tid]);
        out[(size_t)q * 32 + tid] = v;
    }
}

// ---------------- final BN normalize in place ----------------
__global__ __launch_bounds__(256) void finalbn_kernel(float* __restrict__ out) {
    int e = blockIdx.x * 256 + threadIdx.x;
    int c = e & 31;
    out[e] = fmaf(out[e], g_sc3[c], g_sc3[32 + c]);
}

// ---------------- launcher ----------------
extern "C" void kernel_launch(void* const* d_in, const int* in_sizes, int n_in,
                              void* d_out, int out_size) {
    const float* xyz    = (const float*)d_in[0];
    const float* points = (const float*)d_in[1];
    const float* W1     = (const float*)d_in[2];
    const float* b1     = (const float*)d_in[3];
    const float* g1     = (const float*)d_in[4];
    const float* be1    = (const float*)d_in[5];
    const float* W2     = (const float*)d_in[6];
    const float* b2     = (const float*)d_in[7];
    const float* g2     = (const float*)d_in[8];
    const float* be2    = (const float*)d_in[9];
    const float* W3     = (const float*)d_in[10];
    const float* b3     = (const float*)d_in[11];
    const float* gbn    = (const float*)d_in[12];
    const float* bbn    = (const float*)d_in[13];
    float* out = (float*)d_out;

    float* p_h1;  cudaGetSymbolAddress((void**)&p_h1,  g_h1);
    float* p_h2;  cudaGetSymbolAddress((void**)&p_h2,  g_h2);
    float* p_sc1; cudaGetSymbolAddress((void**)&p_sc1, g_sc1);
    float* p_sc2; cudaGetSymbolAddress((void**)&p_sc2, g_sc2);
    float* p_sc3; cudaGetSymbolAddress((void**)&p_sc3, g_sc3);

    knn_kernel<<<1024, 256>>>(xyz);
    stage1_kernel<<<RTOT / 128, 128>>>(xyz, W1, b1);
    stats_kernel<<<2048, 128>>>(p_h1, RTOT);
    finalize_kernel<<<32, 256>>>(1.0f / (float)RTOT, g1, be1, p_sc1);
    stage2_kernel<<<RTOT / 128, 128>>>(W2, b2);
    stats_kernel<<<2048, 128>>>(p_h2, RTOT);
    finalize_kernel<<<32, 256>>>(1.0f / (float)RTOT, g2, be2, p_sc2);
    qcompute_kernel<<<MTOT / 8, 256>>>(points, W3, b3);
    stage3_kernel<<<MTOT, 256>>>(out);
    stats_kernel<<<2048, 128>>>(out, MTOT);
    finalize_kernel<<<32, 256>>>(1.0f / (float)MTOT, gbn, bbn, p_sc3);
    finalbn_kernel<<<RTOT / 256, 256>>>(out);
}

// round 2
// speedup vs baseline: 1.3535x; 1.3535x over previous
#include <cuda_runtime.h>
#include <cuda_fp16.h>
#include <cstdint>

#define BB 4
#define NN 2048
#define KK 32
#define CIN 16
#define COUT 32
#define HH 32
#define RTOT (BB*NN*KK)      // 262144
#define MTOT (BB*NN)         // 8192
#define EPS 1e-5f
#define FULLMASK 0xffffffffu

// ---------------- scratch ----------------
__device__ __align__(16) float   g_h2[(size_t)RTOT*HH];      // 32 MB (pre-BN2 h2)
__device__ __align__(16) __half2 g_Qh[(size_t)MTOT*17*32];   // 17.8 MB: [m][jp=0..16][o]
__device__ int   g_idx[RTOT];
__device__ float g_ps [32*1024];
__device__ float g_ps2[32*1024];
__device__ float g_sc2[64];
__device__ float g_sc3[64];
__device__ __align__(16) float g_W2f[1024];   // sc1-folded W2
__device__ float g_b2f[32];                   // sh1-folded b2

// ---------------- helpers ----------------
__device__ __forceinline__ unsigned long long pack2(float x, float y) {
    unsigned long long r;
    asm("mov.b64 %0, {%1,%2};" : "=l"(r) : "f"(x), "f"(y));
    return r;
}
__device__ __forceinline__ float2 unpack2(unsigned long long v) {
    float2 r;
    asm("mov.b64 {%0,%1}, %2;" : "=f"(r.x), "=f"(r.y) : "l"(v));
    return r;
}
__device__ __forceinline__ unsigned long long ffma2(unsigned long long a, unsigned long long b, unsigned long long c) {
    unsigned long long d;
    asm("fma.rn.f32x2 %0, %1, %2, %3;" : "=l"(d) : "l"(a), "l"(b), "l"(c));
    return d;
}

// warp transpose-reduce: in acc[32] per-lane channel values; out acc[0] = sum over
// lanes of channel `lane`. Fixed order -> deterministic.
__device__ __forceinline__ void tr32(float (&acc)[32], int lane) {
#pragma unroll
    for (int s = 16; s >= 1; s >>= 1) {
#pragma unroll
        for (int i = 0; i < s; i++) {
            float a0 = acc[i], a1 = acc[i + s];
            float give = (lane & s) ? a0 : a1;
            float keep = (lane & s) ? a1 : a0;
            acc[i] = keep + __shfl_xor_sync(FULLMASK, give, s);
        }
    }
}

// ---------------- KNN: warp bitonic top-32 ----------------
__device__ __forceinline__ void cas_pair(float& d, int& i, int stride, bool up, int lane) {
    float od = __shfl_xor_sync(FULLMASK, d, stride);
    int   oi = __shfl_xor_sync(FULLMASK, i, stride);
    bool otherSmaller = (od < d) || (od == d && oi < i);
    bool lower = ((lane & stride) == 0);
    bool take = (lower == up) ? otherSmaller : !otherSmaller;
    if (take) { d = od; i = oi; }
}
__device__ __forceinline__ void sort32(float& d, int& i, bool asc, int lane) {
#pragma unroll
    for (int k = 2; k <= 32; k <<= 1) {
        bool up = (((lane & k) == 0) == asc);
#pragma unroll
        for (int s = k >> 1; s > 0; s >>= 1) cas_pair(d, i, s, up, lane);
    }
}
__device__ __forceinline__ void merge32(float& d, int& i, int lane) {
#pragma unroll
    for (int s = 16; s > 0; s >>= 1) cas_pair(d, i, s, true, lane);
}

__global__ __launch_bounds__(256) void knn_kernel(const float* __restrict__ xyz) {
    __shared__ float4 sp4[NN];   // x,y,z,|p|^2
    int b = blockIdx.x >> 8;
    int nbase = (blockIdx.x & 255) * 8;
    int tid = threadIdx.x;
    for (int i = tid; i < NN; i += 256) {
        const float* p = xyz + ((size_t)b * NN + i) * 3;
        float x = p[0], y = p[1], z = p[2];
        sp4[i] = make_float4(x, y, z, x * x + y * y + z * z);
    }
    __syncthreads();
    int w = tid >> 5, lane = tid & 31;
    int n = nbase + w;
    float4 qp = sp4[n];

    int j = lane;
    float4 t0 = sp4[j];
    float d = fmaf(-2.f, qp.x * t0.x + qp.y * t0.y + qp.z * t0.z, qp.w + t0.w);
    int di = j;
    sort32(d, di, true, lane);

    for (int c = 1; c < 64; c++) {
        j = c * 32 + lane;
        float4 t = sp4[j];
        float cd = fmaf(-2.f, qp.x * t.x + qp.y * t.y + qp.z * t.z, qp.w + t.w);
        int ci = j;
        float kmax = __shfl_sync(FULLMASK, d, 31);
        if (__any_sync(FULLMASK, cd < kmax)) {
            sort32(cd, ci, false, lane);
            bool less = (cd < d) || (cd == d && ci < di);
            if (less) { d = cd; di = ci; }
            merge32(d, di, lane);
        }
    }
    g_idx[((size_t)b * NN + n) * KK + lane] = di;
}

// ---------------- statsA: h1 stats on the fly (no h1 storage) ----------------
__global__ __launch_bounds__(256) void statsA_kernel(const float* __restrict__ xyz,
                                                     const float* __restrict__ W1,
                                                     const float* __restrict__ b1) {
    float s[32], s2[32];
#pragma unroll
    for (int c = 0; c < 32; c++) { s[c] = 0.f; s2[c] = 0.f; }
    int tid = threadIdx.x;
    int t0 = blockIdx.x * 256 + tid;
    float rx[4], ry[4], rz[4];
#pragma unroll
    for (int i = 0; i < 4; i++) {
        int r = t0 + i * 65536;
        int b = r >> 16, n = (r >> 5) & 2047, m = g_idx[r];
        const float* pc = xyz + (size_t)((b << 11) + n) * 3;
        const float* pn = xyz + (size_t)((b << 11) + m) * 3;
        rx[i] = pn[0] - pc[0]; ry[i] = pn[1] - pc[1]; rz[i] = pn[2] - pc[2];
    }
#pragma unroll
    for (int c = 0; c < 32; c++) {
        float w0 = __ldg(W1 + c), w1 = __ldg(W1 + 32 + c), w2 = __ldg(W1 + 64 + c), bb = __ldg(b1 + c);
#pragma unroll
        for (int i = 0; i < 4; i++) {
            float z = fmaf(rx[i], w0, fmaf(ry[i], w1, fmaf(rz[i], w2, bb)));
            float v = fmaxf(z, 0.f);
            s[c] += v; s2[c] = fmaf(v, v, s2[c]);
        }
    }
    int lane = tid & 31, w = tid >> 5;
    tr32(s, lane); tr32(s2, lane);
    __shared__ float red[2][8][32];
    red[0][w][lane] = s[0]; red[1][w][lane] = s2[0];
    __syncthreads();
    if (tid < 32) {
        float a = 0.f, a2 = 0.f;
#pragma unroll
        for (int ww = 0; ww < 8; ww++) { a += red[0][ww][tid]; a2 += red[1][ww][tid]; }
        g_ps [tid * 256 + blockIdx.x] = a;
        g_ps2[tid * 256 + blockIdx.x] = a2;
    }
}

// ---------------- fin1: BN1 scale/shift folded into W2f/b2f ----------------
__global__ __launch_bounds__(1024) void fin1_kernel(const float* __restrict__ g1,
                                                    const float* __restrict__ be1,
                                                    const float* __restrict__ W2,
                                                    const float* __restrict__ b2) {
    __shared__ float ssc[32], ssh[32];
    int tid = threadIdx.x, w = tid >> 5, l = tid & 31;
    float s = 0.f, s2 = 0.f;
#pragma unroll
    for (int i = l; i < 256; i += 32) { s += g_ps[w * 256 + i]; s2 += g_ps2[w * 256 + i]; }
#pragma unroll
    for (int o = 16; o >= 1; o >>= 1) {
        s  += __shfl_down_sync(FULLMASK, s, o);
        s2 += __shfl_down_sync(FULLMASK, s2, o);
    }
    if (l == 0) {
        const float invc = 1.f / (float)RTOT;
        float mean = s * invc;
        float var  = s2 * invc - mean * mean;
        float iv = rsqrtf(var + EPS);
        float sc = g1[w] * iv;
        ssc[w] = sc;
        ssh[w] = fmaf(-mean, sc, be1[w]);
    }
    __syncthreads();
    g_W2f[tid] = ssc[tid >> 5] * W2[tid];
    // b2f[w] = b2[w] + sum_j ssh[j] * W2[j*32+w]
    float v = ssh[l] * W2[l * 32 + w];
#pragma unroll
    for (int o = 16; o >= 1; o >>= 1) v += __shfl_down_sync(FULLMASK, v, o);
    if (l == 0) g_b2f[w] = b2[w] + v;
}

// ---------------- generic finalize: partials -> scale/shift ----------------
__global__ __launch_bounds__(1024) void fin_kernel(int G, float invc,
                                                   const float* __restrict__ gamma,
                                                   const float* __restrict__ beta,
                                                   float* __restrict__ scsh) {
    int tid = threadIdx.x, w = tid >> 5, l = tid & 31;
    float s = 0.f, s2 = 0.f;
    for (int i = l; i < G; i += 32) { s += g_ps[w * G + i]; s2 += g_ps2[w * G + i]; }
#pragma unroll
    for (int o = 16; o >= 1; o >>= 1) {
        s  += __shfl_down_sync(FULLMASK, s, o);
        s2 += __shfl_down_sync(FULLMASK, s2, o);
    }
    if (l == 0) {
        float mean = s * invc;
        float var  = s2 * invc - mean * mean;
        float iv = rsqrtf(var + EPS);
        float sc = gamma[w] * iv;
        scsh[w]      = sc;
        scsh[32 + w] = fmaf(-mean, sc, beta[w]);
    }
}

// ---------------- stage2: recompute h1, apply folded BN1+W2, relu, stats ----------------
__global__ __launch_bounds__(256) void stage2_kernel(const float* __restrict__ xyz,
                                                     const float* __restrict__ W1,
                                                     const float* __restrict__ b1) {
    __shared__ __align__(16) float sW2f[1024];
    __shared__ float sb2f[32];
    __shared__ float sW1[96], sb1[32];
    __shared__ float red[2][8][32];
    int tid = threadIdx.x;
    ((float4*)sW2f)[tid] = ((const float4*)g_W2f)[tid & 255];
    if (tid < 96) sW1[tid] = W1[tid];
    else if (tid < 128) sb1[tid - 96] = b1[tid - 96];
    else if (tid < 160) sb2f[tid - 128] = g_b2f[tid - 128];
    __syncthreads();

    int r = blockIdx.x * 256 + tid;
    int b = r >> 16, n = (r >> 5) & 2047, m = g_idx[r];
    const float* pc = xyz + (size_t)((b << 11) + n) * 3;
    const float* pn = xyz + (size_t)((b << 11) + m) * 3;
    float rx = pn[0] - pc[0], ry = pn[1] - pc[1], rz = pn[2] - pc[2];

    float h[32];
#pragma unroll
    for (int c = 0; c < 32; c++)
        h[c] = fmaxf(fmaf(rx, sW1[c], fmaf(ry, sW1[32 + c], fmaf(rz, sW1[64 + c], sb1[c]))), 0.f);

    unsigned long long acc[16];
#pragma unroll
    for (int q = 0; q < 16; q++) acc[q] = pack2(sb2f[2 * q], sb2f[2 * q + 1]);
    const unsigned long long* w2p = (const unsigned long long*)sW2f;
#pragma unroll
    for (int j = 0; j < 32; j++) {
        unsigned long long hv = pack2(h[j], h[j]);
        const unsigned long long* row = w2p + j * 16;
#pragma unroll
        for (int q = 0; q < 16; q++) acc[q] = ffma2(hv, row[q], acc[q]);
    }

    float v[32];
#pragma unroll
    for (int q = 0; q < 16; q++) {
        float2 p = unpack2(acc[q]);
        v[2 * q]     = fmaxf(p.x, 0.f);
        v[2 * q + 1] = fmaxf(p.y, 0.f);
    }
    float4* o = (float4*)(g_h2 + (size_t)r * 32);
#pragma unroll
    for (int q = 0; q < 8; q++)
        o[q] = make_float4(v[4 * q], v[4 * q + 1], v[4 * q + 2], v[4 * q + 3]);

    float s2[32];
#pragma unroll
    for (int c = 0; c < 32; c++) s2[c] = v[c] * v[c];
    int lane = tid & 31, w = tid >> 5;
    tr32(v, lane); tr32(s2, lane);
    red[0][w][lane] = v[0]; red[1][w][lane] = s2[0];
    __syncthreads();
    if (tid < 32) {
        float a = 0.f, a2 = 0.f;
#pragma unroll
        for (int ww = 0; ww < 8; ww++) { a += red[0][ww][tid]; a2 += red[1][ww][tid]; }
        g_ps [tid * 1024 + blockIdx.x] = a;
        g_ps2[tid * 1024 + blockIdx.x] = a2;
    }
}

// ---------------- qcompute: Qh[m][jp][o] = half2(sc2-scaled Q pairs); row16 = pb3 + sh2.Q ----------------
__global__ __launch_bounds__(256) void qcompute_kernel(const float* __restrict__ points,
                                                       const float* __restrict__ W3,
                                                       const float* __restrict__ b3) {
    __shared__ float sp[8][16];
    __shared__ float ssc[32], ssh[32];
    __shared__ float r16p[8][8][32];   // [jg][m][o]
    int tid = threadIdx.x;
    int mg0 = blockIdx.x * 8;
    if (tid < 128) sp[tid >> 4][tid & 15] = points[(size_t)(mg0 + (tid >> 4)) * CIN + (tid & 15)];
    else if (tid < 160) { ssc[tid - 128] = g_sc2[tid - 128]; ssh[tid - 128] = g_sc2[32 + tid - 128]; }
    __syncthreads();

    int o = tid & 31, jg = tid >> 5, j0 = jg * 4;
    float acc[8][4];
#pragma unroll
    for (int m = 0; m < 8; m++)
#pragma unroll
        for (int jj = 0; jj < 4; jj++) acc[m][jj] = 0.f;

#pragma unroll
    for (int c = 0; c < 16; c++) {
        float w0 = __ldg(W3 + (size_t)(j0 + 0) * 512 + c * 32 + o);
        float w1 = __ldg(W3 + (size_t)(j0 + 1) * 512 + c * 32 + o);
        float w2 = __ldg(W3 + (size_t)(j0 + 2) * 512 + c * 32 + o);
        float w3 = __ldg(W3 + (size_t)(j0 + 3) * 512 + c * 32 + o);
#pragma unroll
        for (int m = 0; m < 8; m++) {
            float pm = sp[m][c];
            acc[m][0] = fmaf(pm, w0, acc[m][0]);
            acc[m][1] = fmaf(pm, w1, acc[m][1]);
            acc[m][2] = fmaf(pm, w2, acc[m][2]);
            acc[m][3] = fmaf(pm, w3, acc[m][3]);
        }
    }
    float c0 = ssc[j0], c1 = ssc[j0 + 1], c2 = ssc[j0 + 2], c3 = ssc[j0 + 3];
    float h0 = ssh[j0], h1 = ssh[j0 + 1], h2v = ssh[j0 + 2], h3 = ssh[j0 + 3];
#pragma unroll
    for (int m = 0; m < 8; m++) {
        size_t base = (size_t)(mg0 + m) * 544;
        g_Qh[base + (size_t)(jg * 2) * 32 + o]     = __floats2half2_rn(acc[m][0] * c0, acc[m][1] * c1);
        g_Qh[base + (size_t)(jg * 2 + 1) * 32 + o] = __floats2half2_rn(acc[m][2] * c2, acc[m][3] * c3);
        r16p[jg][m][o] = fmaf(h0, acc[m][0], fmaf(h1, acc[m][1], fmaf(h2v, acc[m][2], h3 * acc[m][3])));
    }
    __syncthreads();
    {
        int m = tid >> 5;
        float s = 0.f;
#pragma unroll
        for (int g = 0; g < 8; g++) s += r16p[g][m][o];
        float pb = 0.f;
#pragma unroll
        for (int c = 0; c < 16; c++) pb = fmaf(sp[m][c], __ldg(b3 + c * 32 + o), pb);
        g_Qh[(size_t)(mg0 + m) * 544 + 512 + o] = __floats2half2_rn(s + pb, 0.f);
    }
}

// ---------------- stage3: out[q,o] = max_k sum_jp hpair . Qh[m_k][jp][o] ----------------
__global__ __launch_bounds__(256) void stage3_kernel(float* __restrict__ out) {
    __shared__ float2 sH[32 * 17];
    __shared__ int sidx[32];
    __shared__ float wmax[8][32];
    int tid = threadIdx.x;
    int q = blockIdx.x;
    size_t r0 = (size_t)q * KK;
    if (tid < 32) sidx[tid] = g_idx[r0 + tid];
    for (int t = tid; t < 512; t += 256) {
        int k = t >> 4, jp = t & 15;
        sH[k * 17 + jp] = ((const float2*)(g_h2 + (r0 + k) * 32))[jp];
    }
    if (tid < 32) sH[tid * 17 + 16] = make_float2(1.f, 0.f);
    __syncthreads();

    int w = tid >> 5, o = tid & 31, b = q >> 11;
    float vmax = -3.4e38f;
#pragma unroll
    for (int kk = 0; kk < 4; kk++) {
        int k = w + kk * 8;
        int m = sidx[k];
        const __half2* Qp = g_Qh + (size_t)((b << 11) + m) * 544 + o;
        float acc = 0.f;
#pragma unroll
        for (int jp = 0; jp < 17; jp++) {
            float2 hv = sH[k * 17 + jp];
            float2 qf = __half22float2(Qp[(size_t)jp * 32]);
            acc = fmaf(hv.x, qf.x, fmaf(hv.y, qf.y, acc));
        }
        vmax = fmaxf(vmax, acc);
    }
    wmax[w][o] = vmax;
    __syncthreads();
    if (tid < 32) {
        float v = wmax[0][tid];
#pragma unroll
        for (int i = 1; i < 8; i++) v = fmaxf(v, wmax[i][tid]);
        out[(size_t)q * 32 + tid] = v;
    }
}

// ---------------- statsC over out (8192 rows) ----------------
__global__ __launch_bounds__(256) void statsC_kernel(const float* __restrict__ out) {
    int tid = threadIdx.x;
    int q = blockIdx.x * 256 + tid;
    float v[32], s2[32];
    const float4* p = (const float4*)(out + (size_t)q * 32);
#pragma unroll
    for (int i = 0; i < 8; i++) {
        float4 x = p[i];
        v[4 * i] = x.x; v[4 * i + 1] = x.y; v[4 * i + 2] = x.z; v[4 * i + 3] = x.w;
    }
#pragma unroll
    for (int c = 0; c < 32; c++) s2[c] = v[c] * v[c];
    int lane = tid & 31, w = tid >> 5;
    tr32(v, lane); tr32(s2, lane);
    __shared__ float red[2][8][32];
    red[0][w][lane] = v[0]; red[1][w][lane] = s2[0];
    __syncthreads();
    if (tid < 32) {
        float a = 0.f, a2 = 0.f;
#pragma unroll
        for (int ww = 0; ww < 8; ww++) { a += red[0][ww][tid]; a2 += red[1][ww][tid]; }
        g_ps [tid * 32 + blockIdx.x] = a;
        g_ps2[tid * 32 + blockIdx.x] = a2;
    }
}

// ---------------- final BN in place ----------------
__global__ __launch_bounds__(256) void finalbn_kernel(float* __restrict__ out) {
    int e = blockIdx.x * 256 + threadIdx.x;   // float4 index
    float4 v = ((float4*)out)[e];
    int c = (e * 4) & 31;
    v.x = fmaf(v.x, g_sc3[c],     g_sc3[32 + c]);
    v.y = fmaf(v.y, g_sc3[c + 1], g_sc3[33 + c]);
    v.z = fmaf(v.z, g_sc3[c + 2], g_sc3[34 + c]);
    v.w = fmaf(v.w, g_sc3[c + 3], g_sc3[35 + c]);
    ((float4*)out)[e] = v;
}

// ---------------- launcher ----------------
extern "C" void kernel_launch(void* const* d_in, const int* in_sizes, int n_in,
                              void* d_out, int out_size) {
    const float* xyz    = (const float*)d_in[0];
    const float* points = (const float*)d_in[1];
    const float* W1     = (const float*)d_in[2];
    const float* b1     = (const float*)d_in[3];
    const float* g1     = (const float*)d_in[4];
    const float* be1    = (const float*)d_in[5];
    const float* W2     = (const float*)d_in[6];
    const float* b2     = (const float*)d_in[7];
    const float* g2     = (const float*)d_in[8];
    const float* be2    = (const float*)d_in[9];
    const float* W3     = (const float*)d_in[10];
    const float* b3     = (const float*)d_in[11];
    const float* gbn    = (const float*)d_in[12];
    const float* bbn    = (const float*)d_in[13];
    float* out = (float*)d_out;

    float* p_sc2; cudaGetSymbolAddress((void**)&p_sc2, g_sc2);
    float* p_sc3; cudaGetSymbolAddress((void**)&p_sc3, g_sc3);

    knn_kernel   <<<1024, 256>>>(xyz);
    statsA_kernel<<<256, 256>>>(xyz, W1, b1);
    fin1_kernel  <<<1, 1024>>>(g1, be1, W2, b2);
    stage2_kernel<<<1024, 256>>>(xyz, W1, b1);
    fin_kernel   <<<1, 1024>>>(1024, 1.f / (float)RTOT, g2, be2, p_sc2);
    qcompute_kernel<<<MTOT / 8, 256>>>(points, W3, b3);
    stage3_kernel<<<MTOT, 256>>>(out);
    statsC_kernel<<<32, 256>>>(out);
    fin_kernel   <<<1, 1024>>>(32, 1.f / (float)MTOT, gbn, bbn, p_sc3);
    finalbn_kernel<<<256, 256>>>(out);
}